// round 7
// baseline (speedup 1.0000x reference)
#include <cuda_runtime.h>
#include <cuda_fp16.h>
#include <cstdint>

#define BB 4
#define NA 211200
#define CC 256
#define HH 200
#define WW 176
#define KK 4096
#define PLANE (HH * WW)            // 35200 floats

#define NTHREADS 512
#define DEC_BOX_PER_BLK 512
#define DEC_BLOCKS (BB * NA / DEC_BOX_PER_BLK)  // 1650
#define GATHER_BLOCKS (BB * CC)                 // 1024
#define SMEM_BYTES (PLANE * 2)     // 70400 B (fp16 plane) >= 43008 B decode scratch

// ---------------------------------------------------------------------------
// Inline bilinear param computation for one keypoint (replicates reference:
// clamp -> normalize with dims-2 divisor quirk -> flip -> grid_sample
// align_corners=True, zeros padding).
// ---------------------------------------------------------------------------
__device__ __forceinline__ void kp_params(float kx, float ky,
                                          int4& off, float4& w) {
    const float inv_px = 1.0f / (0.05f * 8.0f);
    float indx = kx * inv_px;
    float indy = (ky + 40.0f) * inv_px;
    indx = fminf(fmaxf(indx, 0.0f), (float)(WW - 1));
    indy = fminf(fmaxf(indy, 0.0f), (float)(HH - 1));

    float g0 = 2.0f * (indy / (float)(HH - 2)) - 1.0f;
    float g1 = 2.0f * (indx / (float)(WW - 2)) - 1.0f;
    float ix = (g0 + 1.0f) * 0.5f * (float)(WW - 1);
    float iy = (g1 + 1.0f) * 0.5f * (float)(HH - 1);

    float x0f = floorf(ix);
    float y0f = floorf(iy);
    float wx = ix - x0f;
    float wy = iy - y0f;
    int x0 = (int)x0f, y0 = (int)y0f;
    int x1 = x0 + 1, y1 = y0 + 1;

    bool vx0 = (x0 >= 0) && (x0 <= WW - 1);
    bool vx1 = (x1 >= 0) && (x1 <= WW - 1);
    bool vy0 = (y0 >= 0) && (y0 <= HH - 1);
    bool vy1 = (y1 >= 0) && (y1 <= HH - 1);
    int cx0 = min(max(x0, 0), WW - 1);
    int cx1 = min(max(x1, 0), WW - 1);
    int cy0 = min(max(y0, 0), HH - 1);
    int cy1 = min(max(y1, 0), HH - 1);

    off.x = cy0 * WW + cx0;  w.x = (vy0 && vx0) ? (1.0f - wx) * (1.0f - wy) : 0.0f;
    off.y = cy0 * WW + cx1;  w.y = (vy0 && vx1) ? wx * (1.0f - wy)          : 0.0f;
    off.z = cy1 * WW + cx0;  w.z = (vy1 && vx0) ? (1.0f - wx) * wy          : 0.0f;
    off.w = cy1 * WW + cx1;  w.w = (vy1 && vx1) ? wx * wy                   : 0.0f;
}

// ---------------------------------------------------------------------------
// Single fused kernel: decode blocks [0, DEC_BLOCKS) then gather blocks.
// ---------------------------------------------------------------------------
__global__ void __launch_bounds__(NTHREADS) fused_kernel(
    const float* __restrict__ fm,
    const float* __restrict__ deltas,
    const float* __restrict__ anchors,
    const float* __restrict__ kp,
    float* __restrict__ out_feats,
    float* __restrict__ out_boxes) {
    extern __shared__ char smem_raw[];
    int t = threadIdx.x;

    if (blockIdx.x >= DEC_BLOCKS) {
        // ------------------------- gather branch --------------------------
        __half* splane = (__half*)smem_raw;
        int plane = blockIdx.x - DEC_BLOCKS;  // = b * CC + c
        int b = plane >> 8;
        const float4* pf4 = (const float4*)(fm + (size_t)plane * PLANE);
        float* po = out_feats + (size_t)plane * KK;
        const float* kpb = kp + (size_t)b * KK * 3;

        // Stage plane as fp16: 8800 float4 = 17*512 + 96.
        __half2* s2 = (__half2*)splane;
#pragma unroll
        for (int j = 0; j < 17; ++j) {
            int i = t + j * NTHREADS;
            float4 v = pf4[i];
            s2[i * 2 + 0] = __floats2half2_rn(v.x, v.y);
            s2[i * 2 + 1] = __floats2half2_rn(v.z, v.w);
        }
        if (t < 96) {
            int i = t + 17 * NTHREADS;
            float4 v = pf4[i];
            s2[i * 2 + 0] = __floats2half2_rn(v.x, v.y);
            s2[i * 2 + 1] = __floats2half2_rn(v.z, v.w);
        }
        __syncthreads();

        // Gather: params recomputed inline (kp is L2-resident, ALU is idle).
#pragma unroll
        for (int it = 0; it < KK / NTHREADS; ++it) {
            int k = t + it * NTHREADS;
            float kx = __ldg(kpb + (size_t)k * 3 + 0);
            float ky = __ldg(kpb + (size_t)k * 3 + 1);
            int4 o; float4 w;
            kp_params(kx, ky, o, w);
            float v = w.x * __half2float(splane[o.x]);
            v = fmaf(w.y, __half2float(splane[o.y]), v);
            v = fmaf(w.z, __half2float(splane[o.z]), v);
            v = fmaf(w.w, __half2float(splane[o.w]), v);
            po[k] = v;
        }
    } else {
        // ------------------------- decode branch --------------------------
        // 512 boxes per block = 3584 floats per array = 896 float4.
        float* sp = (float*)smem_raw;            // 3584 floats
        float* sa = sp + 3584;
        float* so = sa + 3584;                   // total 43008 B

        size_t base = (size_t)blockIdx.x * (DEC_BOX_PER_BLK * 7);
        const float4* dp = (const float4*)(deltas + base);
        const float4* ap = (const float4*)(anchors + base);
        float4* op = (float4*)(out_boxes + base);

        {
            ((float4*)sp)[t] = dp[t];
            ((float4*)sa)[t] = ap[t];
            int t2 = t + NTHREADS;
            if (t2 < 896) {
                ((float4*)sp)[t2] = dp[t2];
                ((float4*)sa)[t2] = ap[t2];
            }
        }
        __syncthreads();

        {
            const float* p = sp + t * 7;
            const float* a = sa + t * 7;
            float p0 = p[0], p1 = p[1], p2 = p[2], p3 = p[3], p4 = p[4], p5 = p[5], p6 = p[6];
            float a0 = a[0], a1 = a[1], a2 = a[2], a3 = a[3], a4 = a[4], a5 = a[5], a6 = a[6];
            float d = sqrtf(a3 * a3 + a4 * a4);
            float* o = so + t * 7;
            o[0] = fmaf(p0, d, a0);
            o[1] = fmaf(p1, d, a1);
            o[2] = fmaf(p2, a5, a2);
            o[3] = expf(p3) * a3;
            o[4] = expf(p4) * a4;
            o[5] = expf(p5) * a5;
            o[6] = p6 + a6;
        }
        __syncthreads();

        {
            op[t] = ((float4*)so)[t];
            int t2 = t + NTHREADS;
            if (t2 < 896) op[t2] = ((float4*)so)[t2];
        }
    }
}

// ---------------------------------------------------------------------------
extern "C" void kernel_launch(void* const* d_in, const int* in_sizes, int n_in,
                              void* d_out, int out_size) {
    const float* deltas  = (const float*)d_in[0];
    const float* anchors = (const float*)d_in[1];
    const float* fm      = (const float*)d_in[2];
    const float* kp      = (const float*)d_in[3];
    float* out = (float*)d_out;

    float* out_boxes = out;
    float* out_feats = out + (size_t)BB * NA * 7;

    cudaFuncSetAttribute(fused_kernel,
                         cudaFuncAttributeMaxDynamicSharedMemorySize,
                         SMEM_BYTES);

    fused_kernel<<<DEC_BLOCKS + GATHER_BLOCKS, NTHREADS, SMEM_BYTES>>>(
        fm, deltas, anchors, kp, out_feats, out_boxes);
}

// round 8
// speedup vs baseline: 1.0144x; 1.0144x over previous
#include <cuda_runtime.h>
#include <cuda_fp16.h>
#include <cstdint>

#define BB 4
#define NA 211200
#define CC 256
#define HH 200
#define WW 176
#define KK 4096
#define PLANE (HH * WW)            // 35200 floats

#define NTHREADS 512
#define DEC_BOX_PER_BLK 512
#define DEC_BLOCKS (BB * NA / DEC_BOX_PER_BLK)  // 1650
#define GATHER_BLOCKS (BB * CC)                 // 1024
#define SMEM_BYTES (PLANE * 2)     // 70400 B (fp16 plane) >= 43008 B decode scratch

// ---------------------------------------------------------------------------
// Inline bilinear param computation for one keypoint (replicates reference:
// clamp -> normalize with dims-2 divisor quirk -> flip -> grid_sample
// align_corners=True, zeros padding).
// ---------------------------------------------------------------------------
__device__ __forceinline__ void kp_params(float kx, float ky,
                                          int4& off, float4& w) {
    const float inv_px = 1.0f / (0.05f * 8.0f);
    float indx = kx * inv_px;
    float indy = (ky + 40.0f) * inv_px;
    indx = fminf(fmaxf(indx, 0.0f), (float)(WW - 1));
    indy = fminf(fmaxf(indy, 0.0f), (float)(HH - 1));

    float g0 = 2.0f * (indy / (float)(HH - 2)) - 1.0f;
    float g1 = 2.0f * (indx / (float)(WW - 2)) - 1.0f;
    float ix = (g0 + 1.0f) * 0.5f * (float)(WW - 1);
    float iy = (g1 + 1.0f) * 0.5f * (float)(HH - 1);

    float x0f = floorf(ix);
    float y0f = floorf(iy);
    float wx = ix - x0f;
    float wy = iy - y0f;
    int x0 = (int)x0f, y0 = (int)y0f;
    int x1 = x0 + 1, y1 = y0 + 1;

    bool vx0 = (x0 >= 0) && (x0 <= WW - 1);
    bool vx1 = (x1 >= 0) && (x1 <= WW - 1);
    bool vy0 = (y0 >= 0) && (y0 <= HH - 1);
    bool vy1 = (y1 >= 0) && (y1 <= HH - 1);
    int cx0 = min(max(x0, 0), WW - 1);
    int cx1 = min(max(x1, 0), WW - 1);
    int cy0 = min(max(y0, 0), HH - 1);
    int cy1 = min(max(y1, 0), HH - 1);

    off.x = cy0 * WW + cx0;  w.x = (vy0 && vx0) ? (1.0f - wx) * (1.0f - wy) : 0.0f;
    off.y = cy0 * WW + cx1;  w.y = (vy0 && vx1) ? wx * (1.0f - wy)          : 0.0f;
    off.z = cy1 * WW + cx0;  w.z = (vy1 && vx0) ? (1.0f - wx) * wy          : 0.0f;
    off.w = cy1 * WW + cx1;  w.w = (vy1 && vx1) ? wx * wy                   : 0.0f;
}

// ---------------------------------------------------------------------------
// Single fused kernel: decode blocks [0, DEC_BLOCKS) then gather blocks.
// ---------------------------------------------------------------------------
__global__ void __launch_bounds__(NTHREADS) fused_kernel(
    const float* __restrict__ fm,
    const float* __restrict__ deltas,
    const float* __restrict__ anchors,
    const float* __restrict__ kp,
    float* __restrict__ out_feats,
    float* __restrict__ out_boxes) {
    extern __shared__ char smem_raw[];
    int t = threadIdx.x;

    if (blockIdx.x >= DEC_BLOCKS) {
        // ------------------------- gather branch --------------------------
        __half* splane = (__half*)smem_raw;
        int plane = blockIdx.x - DEC_BLOCKS;  // = b * CC + c
        int b = plane >> 8;
        const float4* pf4 = (const float4*)(fm + (size_t)plane * PLANE);
        float* po = out_feats + (size_t)plane * KK;
        const float* kpb = kp + (size_t)b * KK * 3;

        // Stage plane as fp16: 8800 float4 = 17*512 + 96.
        __half2* s2 = (__half2*)splane;
#pragma unroll
        for (int j = 0; j < 17; ++j) {
            int i = t + j * NTHREADS;
            float4 v = pf4[i];
            s2[i * 2 + 0] = __floats2half2_rn(v.x, v.y);
            s2[i * 2 + 1] = __floats2half2_rn(v.z, v.w);
        }
        if (t < 96) {
            int i = t + 17 * NTHREADS;
            float4 v = pf4[i];
            s2[i * 2 + 0] = __floats2half2_rn(v.x, v.y);
            s2[i * 2 + 1] = __floats2half2_rn(v.z, v.w);
        }
        __syncthreads();

        // Gather: params recomputed inline (kp is L2-resident, ALU is idle).
#pragma unroll
        for (int it = 0; it < KK / NTHREADS; ++it) {
            int k = t + it * NTHREADS;
            float kx = __ldg(kpb + (size_t)k * 3 + 0);
            float ky = __ldg(kpb + (size_t)k * 3 + 1);
            int4 o; float4 w;
            kp_params(kx, ky, o, w);
            float v = w.x * __half2float(splane[o.x]);
            v = fmaf(w.y, __half2float(splane[o.y]), v);
            v = fmaf(w.z, __half2float(splane[o.z]), v);
            v = fmaf(w.w, __half2float(splane[o.w]), v);
            po[k] = v;
        }
    } else {
        // ------------------------- decode branch --------------------------
        // 512 boxes per block = 3584 floats per array = 896 float4.
        float* sp = (float*)smem_raw;            // 3584 floats
        float* sa = sp + 3584;
        float* so = sa + 3584;                   // total 43008 B

        size_t base = (size_t)blockIdx.x * (DEC_BOX_PER_BLK * 7);
        const float4* dp = (const float4*)(deltas + base);
        const float4* ap = (const float4*)(anchors + base);
        float4* op = (float4*)(out_boxes + base);

        {
            ((float4*)sp)[t] = dp[t];
            ((float4*)sa)[t] = ap[t];
            int t2 = t + NTHREADS;
            if (t2 < 896) {
                ((float4*)sp)[t2] = dp[t2];
                ((float4*)sa)[t2] = ap[t2];
            }
        }
        __syncthreads();

        {
            const float* p = sp + t * 7;
            const float* a = sa + t * 7;
            float p0 = p[0], p1 = p[1], p2 = p[2], p3 = p[3], p4 = p[4], p5 = p[5], p6 = p[6];
            float a0 = a[0], a1 = a[1], a2 = a[2], a3 = a[3], a4 = a[4], a5 = a[5], a6 = a[6];
            float d = sqrtf(a3 * a3 + a4 * a4);
            float* o = so + t * 7;
            o[0] = fmaf(p0, d, a0);
            o[1] = fmaf(p1, d, a1);
            o[2] = fmaf(p2, a5, a2);
            o[3] = expf(p3) * a3;
            o[4] = expf(p4) * a4;
            o[5] = expf(p5) * a5;
            o[6] = p6 + a6;
        }
        __syncthreads();

        {
            op[t] = ((float4*)so)[t];
            int t2 = t + NTHREADS;
            if (t2 < 896) op[t2] = ((float4*)so)[t2];
        }
    }
}

// ---------------------------------------------------------------------------
extern "C" void kernel_launch(void* const* d_in, const int* in_sizes, int n_in,
                              void* d_out, int out_size) {
    const float* deltas  = (const float*)d_in[0];
    const float* anchors = (const float*)d_in[1];
    const float* fm      = (const float*)d_in[2];
    const float* kp      = (const float*)d_in[3];
    float* out = (float*)d_out;

    float* out_boxes = out;
    float* out_feats = out + (size_t)BB * NA * 7;

    cudaFuncSetAttribute(fused_kernel,
                         cudaFuncAttributeMaxDynamicSharedMemorySize,
                         SMEM_BYTES);

    fused_kernel<<<DEC_BLOCKS + GATHER_BLOCKS, NTHREADS, SMEM_BYTES>>>(
        fm, deltas, anchors, kp, out_feats, out_boxes);
}